// round 1
// baseline (speedup 1.0000x reference)
#include <cuda_runtime.h>
#include <cuda_bf16.h>
#include <math.h>

// ---------------------------------------------------------------------------
// Problem constants
// ---------------------------------------------------------------------------
#define Bq   2
#define Sq   1024
#define Hq   4096
#define NH   32
#define NKV  8
#define HD   128
#define Gq   4                      // NH / NKV
#define QKVW 6144                   // (NKV*2 + NH) * HD
#define FF   16384
#define Mrows (Bq * Sq)             // 2048
#define EPS  1e-5f
#define ATTN_SCALE 0.08838834764831845f   // 1/sqrt(128)

// ---------------------------------------------------------------------------
// Scratch (device globals — no runtime allocation)
// ---------------------------------------------------------------------------
__device__ float g_attn_in [Mrows * Hq];      // 32 MB
__device__ float g_mlp_in  [Mrows * Hq];      // 32 MB
__device__ float g_qkv     [Mrows * QKVW];    // 48 MB
__device__ float g_q       [(size_t)Bq * NH  * Sq * HD]; // 32 MB
__device__ float g_k       [(size_t)Bq * NKV * Sq * HD]; //  8 MB
__device__ float g_v       [(size_t)Bq * NKV * Sq * HD]; //  8 MB
__device__ float g_ctx     [Mrows * Hq];      // 32 MB
__device__ float g_attn_out[Mrows * Hq];      // 32 MB
__device__ float g_fc      [(size_t)Mrows * FF];         // 128 MB

// ---------------------------------------------------------------------------
// Dual LayerNorm: one block per row, writes attn_in and mlp_in
// ---------------------------------------------------------------------------
__global__ void __launch_bounds__(256)
ln_dual_kernel(const float* __restrict__ x,
               const float* __restrict__ s1, const float* __restrict__ b1,
               const float* __restrict__ s2, const float* __restrict__ b2,
               float* __restrict__ o1, float* __restrict__ o2)
{
    int row = blockIdx.x;
    const float4* xr = (const float4*)(x + (size_t)row * Hq);

    float sum = 0.f, sq = 0.f;
    for (int i = threadIdx.x; i < Hq / 4; i += 256) {
        float4 v = xr[i];
        sum += v.x + v.y + v.z + v.w;
        sq  += v.x*v.x + v.y*v.y + v.z*v.z + v.w*v.w;
    }
    #pragma unroll
    for (int o = 16; o; o >>= 1) {
        sum += __shfl_xor_sync(0xFFFFFFFFu, sum, o);
        sq  += __shfl_xor_sync(0xFFFFFFFFu, sq,  o);
    }
    __shared__ float wsum[8], wsq[8];
    int w = threadIdx.x >> 5, l = threadIdx.x & 31;
    if (l == 0) { wsum[w] = sum; wsq[w] = sq; }
    __syncthreads();
    sum = 0.f; sq = 0.f;
    #pragma unroll
    for (int i = 0; i < 8; i++) { sum += wsum[i]; sq += wsq[i]; }

    float mean = sum * (1.0f / Hq);
    float var  = sq  * (1.0f / Hq) - mean * mean;
    float rstd = rsqrtf(var + EPS);

    const float4* s1r = (const float4*)s1;
    const float4* b1r = (const float4*)b1;
    const float4* s2r = (const float4*)s2;
    const float4* b2r = (const float4*)b2;
    float4* o1r = (float4*)(o1 + (size_t)row * Hq);
    float4* o2r = (float4*)(o2 + (size_t)row * Hq);

    for (int i = threadIdx.x; i < Hq / 4; i += 256) {
        float4 v = xr[i];
        float4 a = s1r[i], c = b1r[i], d = s2r[i], e = b2r[i];
        float nx = (v.x - mean) * rstd;
        float ny = (v.y - mean) * rstd;
        float nz = (v.z - mean) * rstd;
        float nw = (v.w - mean) * rstd;
        float4 r1 = make_float4(nx*a.x + c.x, ny*a.y + c.y, nz*a.z + c.z, nw*a.w + c.w);
        float4 r2 = make_float4(nx*d.x + e.x, ny*d.y + e.y, nz*d.z + e.z, nw*d.w + e.w);
        o1r[i] = r1;
        o2r[i] = r2;
    }
}

// ---------------------------------------------------------------------------
// SGEMM: C[M,N] = A[M,K] @ B[K,N], all row-major.
// 128x128 block, 8x8 per thread (2x2 quads of float4), BK=8, 256 threads.
// EPI: 0 = none, 1 = exact GELU, 2 = C = AB + R1 + R2
// ---------------------------------------------------------------------------
__device__ __forceinline__ float gelu_exact(float x) {
    return 0.5f * x * (1.0f + erff(x * 0.7071067811865475f));
}

template <int EPI>
__global__ void __launch_bounds__(256)
sgemm_kernel(const float* __restrict__ A, const float* __restrict__ Bm,
             float* __restrict__ C, int K, int N,
             const float* __restrict__ R1, const float* __restrict__ R2)
{
    __shared__ float As[8][128];
    __shared__ float Bs[8][128];

    int tid = threadIdx.x;
    int m0 = blockIdx.y * 128;
    int n0 = blockIdx.x * 128;

    int arow = tid >> 1;           // 0..127
    int acol = (tid & 1) * 4;      // 0 or 4
    int brow = tid >> 5;           // 0..7
    int bcol = (tid & 31) * 4;     // 0..124
    int tx = tid & 15, ty = tid >> 4;

    float acc[8][8];
    #pragma unroll
    for (int i = 0; i < 8; i++)
        #pragma unroll
        for (int j = 0; j < 8; j++) acc[i][j] = 0.f;

    const float* Aptr = A + (size_t)(m0 + arow) * K + acol;
    const float* Bptr = Bm + (size_t)brow * N + n0 + bcol;

    for (int k0 = 0; k0 < K; k0 += 8) {
        float4 av = *(const float4*)(Aptr + k0);
        float4 bv = *(const float4*)(Bptr + (size_t)k0 * N);
        As[acol + 0][arow] = av.x;
        As[acol + 1][arow] = av.y;
        As[acol + 2][arow] = av.z;
        As[acol + 3][arow] = av.w;
        *(float4*)&Bs[brow][bcol] = bv;
        __syncthreads();

        #pragma unroll
        for (int kk = 0; kk < 8; kk++) {
            float4 a0 = *(const float4*)&As[kk][ty * 4];
            float4 a1 = *(const float4*)&As[kk][64 + ty * 4];
            float4 b0 = *(const float4*)&Bs[kk][tx * 4];
            float4 b1 = *(const float4*)&Bs[kk][64 + tx * 4];
            float am[8] = {a0.x, a0.y, a0.z, a0.w, a1.x, a1.y, a1.z, a1.w};
            float bn[8] = {b0.x, b0.y, b0.z, b0.w, b1.x, b1.y, b1.z, b1.w};
            #pragma unroll
            for (int i = 0; i < 8; i++)
                #pragma unroll
                for (int j = 0; j < 8; j++)
                    acc[i][j] += am[i] * bn[j];
        }
        __syncthreads();
    }

    #pragma unroll
    for (int i = 0; i < 8; i++) {
        int m = m0 + ((i < 4) ? (ty * 4 + i) : (64 + ty * 4 + i - 4));
        float* crow = C + (size_t)m * N + n0;
        float4 v0 = make_float4(acc[i][0], acc[i][1], acc[i][2], acc[i][3]);
        float4 v1 = make_float4(acc[i][4], acc[i][5], acc[i][6], acc[i][7]);
        if (EPI == 1) {
            v0.x = gelu_exact(v0.x); v0.y = gelu_exact(v0.y);
            v0.z = gelu_exact(v0.z); v0.w = gelu_exact(v0.w);
            v1.x = gelu_exact(v1.x); v1.y = gelu_exact(v1.y);
            v1.z = gelu_exact(v1.z); v1.w = gelu_exact(v1.w);
        }
        if (EPI == 2) {
            size_t base = (size_t)m * N + n0;
            float4 r10 = *(const float4*)(R1 + base + tx * 4);
            float4 r11 = *(const float4*)(R1 + base + 64 + tx * 4);
            float4 r20 = *(const float4*)(R2 + base + tx * 4);
            float4 r21 = *(const float4*)(R2 + base + 64 + tx * 4);
            v0.x += r10.x + r20.x; v0.y += r10.y + r20.y;
            v0.z += r10.z + r20.z; v0.w += r10.w + r20.w;
            v1.x += r11.x + r21.x; v1.y += r11.y + r21.y;
            v1.z += r11.z + r21.z; v1.w += r11.w + r21.w;
        }
        *(float4*)(crow + tx * 4)      = v0;
        *(float4*)(crow + 64 + tx * 4) = v1;
    }
}

// ---------------------------------------------------------------------------
// RoPE + head split: qkv[b,s, NKV, G+2, HD] -> q[b,h,s,d], k/v[b,kv,s,d]
// ---------------------------------------------------------------------------
__global__ void __launch_bounds__(128)
rope_kernel(const float* __restrict__ qkv,
            const float* __restrict__ sint, const float* __restrict__ cost,
            const int* __restrict__ pos_ids,
            float* __restrict__ Qo, float* __restrict__ Ko, float* __restrict__ Vo)
{
    int d = threadIdx.x;
    int idx = blockIdx.x;
    int kvh = idx % NKV; idx /= NKV;
    int s = idx % Sq;
    int b = idx / Sq;

    int pos = pos_ids[b * Sq + s];
    float sn = sint[pos * HD + d];
    float cs = cost[pos * HD + d];
    int dro = (d < 64) ? (d + 64) : (d - 64);
    float sgn = (d < 64) ? -1.f : 1.f;

    const float* base = qkv + (size_t)(b * Sq + s) * QKVW + kvh * (Gq + 2) * HD;

    // K (with rope) and V
    float kx = base[Gq * HD + d];
    float ko = base[Gq * HD + dro];
    size_t kvidx = ((size_t)(b * NKV + kvh) * Sq + s) * HD + d;
    Ko[kvidx] = kx * cs + sgn * ko * sn;
    Vo[kvidx] = base[(Gq + 1) * HD + d];

    // Q heads of this group (with rope)
    #pragma unroll
    for (int g = 0; g < Gq; g++) {
        int h = kvh * Gq + g;
        float qx = base[g * HD + d];
        float qo = base[g * HD + dro];
        Qo[((size_t)(b * NH + h) * Sq + s) * HD + d] = qx * cs + sgn * qo * sn;
    }
}

// ---------------------------------------------------------------------------
// Flash-attention-style kernel: one CTA per (b, h, 64-query tile).
// Streams 64-key chunks with online softmax. Causal + key-padding mask.
// ---------------------------------------------------------------------------
#define QT 64
#define KT 64
#define DPAD 132
#define SPAD 66
#define ATTN_SMEM ((3 * QT * DPAD + QT * SPAD + 3 * QT) * 4)

__global__ void __launch_bounds__(256)
attn_kernel(const float* __restrict__ Q, const float* __restrict__ Kg,
            const float* __restrict__ Vg, const int* __restrict__ amask,
            float* __restrict__ ctx)
{
    extern __shared__ float sm[];
    float* Qs   = sm;                         // QT * DPAD
    float* Ks   = Qs + QT * DPAD;             // KT * DPAD
    float* Vs   = Ks + KT * DPAD;             // KT * DPAD
    float* Ss   = Vs + KT * DPAD;             // QT * SPAD
    float* rowm = Ss + QT * SPAD;
    float* rowl = rowm + QT;
    float* rowc = rowl + QT;

    int t  = threadIdx.x;
    int q0 = blockIdx.x * QT;
    int h  = blockIdx.y;
    int b  = blockIdx.z;
    int kv = h >> 2;                          // G = 4

    const float* Qb = Q  + ((size_t)(b * NH  + h ) * Sq + q0) * HD;
    const float* Kb = Kg + ((size_t)(b * NKV + kv) * Sq) * HD;
    const float* Vb = Vg + ((size_t)(b * NKV + kv) * Sq) * HD;

    // load Q tile (64 x 128)
    for (int i = t; i < QT * (HD / 4); i += 256) {
        int r = i >> 5;            // /32
        int c = (i & 31) * 4;
        *(float4*)&Qs[r * DPAD + c] = *(const float4*)(Qb + (size_t)r * HD + c);
    }
    if (t < QT) { rowm[t] = -1e30f; rowl[t] = 0.f; }

    float4 o[8];
    #pragma unroll
    for (int i = 0; i < 8; i++) o[i] = make_float4(0.f, 0.f, 0.f, 0.f);

    int cg = t & 31;      // output col group (d0 = cg*4)
    int rb = t >> 5;      // output row base (rows rb + 8*i)
    int qr = t >> 2;      // score row
    int kb = t & 3;       // score col base (cols kb + 4*j)

    __syncthreads();

    int kend = q0 + QT;
    for (int k0 = 0; k0 < kend; k0 += KT) {
        // load K, V chunk
        for (int i = t; i < KT * (HD / 4); i += 256) {
            int r = i >> 5;
            int c = (i & 31) * 4;
            *(float4*)&Ks[r * DPAD + c] = *(const float4*)(Kb + (size_t)(k0 + r) * HD + c);
            *(float4*)&Vs[r * DPAD + c] = *(const float4*)(Vb + (size_t)(k0 + r) * HD + c);
        }
        __syncthreads();

        // scores: each thread computes 16 (qr, kb+4j)
        float acc[16];
        #pragma unroll
        for (int j = 0; j < 16; j++) acc[j] = 0.f;
        const float4* qrow = (const float4*)&Qs[qr * DPAD];
        for (int d4 = 0; d4 < 32; d4++) {
            float4 qv = qrow[d4];
            #pragma unroll
            for (int j = 0; j < 16; j++) {
                float4 kvv = *(const float4*)&Ks[(kb + 4 * j) * DPAD + d4 * 4];
                acc[j] += qv.x * kvv.x + qv.y * kvv.y + qv.z * kvv.z + qv.w * kvv.w;
            }
        }
        int qg = q0 + qr;
        #pragma unroll
        for (int j = 0; j < 16; j++) {
            int kk = kb + 4 * j;
            int kg = k0 + kk;
            bool valid = (kg <= qg) && (amask[b * Sq + kg] > 0);
            Ss[qr * SPAD + kk] = valid ? acc[j] * ATTN_SCALE : -1e30f;
        }
        __syncthreads();

        // online softmax per row
        if (t < QT) {
            float m_old = rowm[t];
            float m = m_old;
            #pragma unroll 8
            for (int k = 0; k < KT; k++) m = fmaxf(m, Ss[t * SPAD + k]);
            float cfac = __expf(m_old - m);
            float lsum = 0.f;
            #pragma unroll 8
            for (int k = 0; k < KT; k++) {
                float p = __expf(Ss[t * SPAD + k] - m);
                Ss[t * SPAD + k] = p;
                lsum += p;
            }
            rowm[t] = m;
            rowl[t] = rowl[t] * cfac + lsum;
            rowc[t] = cfac;
        }
        __syncthreads();

        // rescale accumulators + P@V
        #pragma unroll
        for (int i = 0; i < 8; i++) {
            int r = rb + 8 * i;
            float cfac = rowc[r];
            float4 ov = o[i];
            ov.x *= cfac; ov.y *= cfac; ov.z *= cfac; ov.w *= cfac;
            const float* srow = &Ss[r * SPAD];
            #pragma unroll 4
            for (int k = 0; k < KT; k++) {
                float p = srow[k];
                float4 vv = *(const float4*)&Vs[k * DPAD + cg * 4];
                ov.x += p * vv.x; ov.y += p * vv.y;
                ov.z += p * vv.z; ov.w += p * vv.w;
            }
            o[i] = ov;
        }
        __syncthreads();
    }

    // write ctx [b, q, h*HD + d]
    #pragma unroll
    for (int i = 0; i < 8; i++) {
        int r = rb + 8 * i;
        float inv = 1.f / rowl[r];
        float4 ov = o[i];
        ov.x *= inv; ov.y *= inv; ov.z *= inv; ov.w *= inv;
        size_t idx = ((size_t)(b * Sq + q0 + r)) * Hq + h * HD + cg * 4;
        *(float4*)&ctx[idx] = ov;
    }
}

// ---------------------------------------------------------------------------
// Launch
// ---------------------------------------------------------------------------
extern "C" void kernel_launch(void* const* d_in, const int* in_sizes, int n_in,
                              void* d_out, int out_size)
{
    const float* hidden  = (const float*)d_in[0];
    const float* w_qkv   = (const float*)d_in[1];
    const float* w_dense = (const float*)d_in[2];
    const float* ln_a_s  = (const float*)d_in[3];
    const float* ln_a_b  = (const float*)d_in[4];
    const float* ln_m_s  = (const float*)d_in[5];
    const float* ln_m_b  = (const float*)d_in[6];
    const float* w_fc    = (const float*)d_in[7];
    const float* w_out   = (const float*)d_in[8];
    const float* sin_tab = (const float*)d_in[9];
    const float* cos_tab = (const float*)d_in[10];
    const int*   amask   = (const int*)d_in[11];
    const int*   pos_ids = (const int*)d_in[12];
    float* out = (float*)d_out;

    float *p_attn_in, *p_mlp_in, *p_qkv, *p_q, *p_k, *p_v, *p_ctx, *p_attn_out, *p_fc;
    cudaGetSymbolAddress((void**)&p_attn_in,  g_attn_in);
    cudaGetSymbolAddress((void**)&p_mlp_in,   g_mlp_in);
    cudaGetSymbolAddress((void**)&p_qkv,      g_qkv);
    cudaGetSymbolAddress((void**)&p_q,        g_q);
    cudaGetSymbolAddress((void**)&p_k,        g_k);
    cudaGetSymbolAddress((void**)&p_v,        g_v);
    cudaGetSymbolAddress((void**)&p_ctx,      g_ctx);
    cudaGetSymbolAddress((void**)&p_attn_out, g_attn_out);
    cudaGetSymbolAddress((void**)&p_fc,       g_fc);

    // 1. parallel layernorms
    ln_dual_kernel<<<Mrows, 256>>>(hidden, ln_a_s, ln_a_b, ln_m_s, ln_m_b,
                                   p_attn_in, p_mlp_in);

    // 2. fused qkv projection
    sgemm_kernel<0><<<dim3(QKVW / 128, Mrows / 128), 256>>>(
        p_attn_in, w_qkv, p_qkv, Hq, QKVW, nullptr, nullptr);

    // 3. rope + head split
    rope_kernel<<<Bq * Sq * NKV, 128>>>(p_qkv, sin_tab, cos_tab, pos_ids,
                                        p_q, p_k, p_v);

    // 4. attention
    cudaFuncSetAttribute(attn_kernel, cudaFuncAttributeMaxDynamicSharedMemorySize,
                         ATTN_SMEM);
    attn_kernel<<<dim3(Sq / QT, NH, Bq), 256, ATTN_SMEM>>>(
        p_q, p_k, p_v, amask, p_ctx);

    // 5. dense projection
    sgemm_kernel<0><<<dim3(Hq / 128, Mrows / 128), 256>>>(
        p_ctx, w_dense, p_attn_out, Hq, Hq, nullptr, nullptr);

    // 6. MLP fc + exact gelu
    sgemm_kernel<1><<<dim3(FF / 128, Mrows / 128), 256>>>(
        p_mlp_in, w_fc, p_fc, Hq, FF, nullptr, nullptr);

    // 7. MLP out + parallel residual (hidden + attn_out + mlp_out) -> d_out
    sgemm_kernel<2><<<dim3(Hq / 128, Mrows / 128), 256>>>(
        p_fc, w_out, out, FF, Hq, hidden, p_attn_out);
}

// round 3
// speedup vs baseline: 2.8739x; 2.8739x over previous
#include <cuda_runtime.h>
#include <cuda_bf16.h>
#include <math.h>
#include <stdint.h>

// ---------------------------------------------------------------------------
// Problem constants
// ---------------------------------------------------------------------------
#define Bq   2
#define Sq   1024
#define Hq   4096
#define NH   32
#define NKV  8
#define HD   128
#define Gq   4
#define QKVW 6144
#define FF   16384
#define Mrows (Bq * Sq)
#define EPS  1e-5f
#define ATTN_SCALE 0.08838834764831845f

// ---------------------------------------------------------------------------
// Helpers
// ---------------------------------------------------------------------------
__device__ __forceinline__ uint32_t smem_u32(const void* p) {
    uint32_t a;
    asm("{ .reg .u64 t; cvta.to.shared.u64 t, %1; cvt.u32.u64 %0, t; }" : "=r"(a) : "l"(p));
    return a;
}
#define CP_ASYNC16(dst, src) \
    asm volatile("cp.async.cg.shared.global [%0], [%1], 16;" :: "r"(dst), "l"(src) : "memory")
#define CP_COMMIT() asm volatile("cp.async.commit_group;" ::: "memory")

__device__ __forceinline__ float tf32r(float x) {
    uint32_t u;
    asm("cvt.rna.tf32.f32 %0, %1;" : "=r"(u) : "f"(x));
    return __uint_as_float(u);
}
__device__ __forceinline__ float gelu_exact(float x) {
    return 0.5f * x * (1.0f + erff(x * 0.7071067811865475f));
}

// ---------------------------------------------------------------------------
// Scratch (device globals)
// ---------------------------------------------------------------------------
__device__ float g_attn_in [Mrows * Hq];
__device__ float g_mlp_in  [Mrows * Hq];
__device__ float g_qkv     [Mrows * QKVW];
__device__ float g_q       [(size_t)Bq * NH  * Sq * HD];
__device__ float g_k       [(size_t)Bq * NKV * Sq * HD];
__device__ float g_v       [(size_t)Bq * NKV * Sq * HD];
__device__ float g_ctx     [Mrows * Hq];
__device__ float g_attn_out[Mrows * Hq];
__device__ float g_fc      [(size_t)Mrows * FF];
// transposed (K-major) tf32-rounded weights
__device__ float g_wqkv_t  [(size_t)QKVW * Hq];
__device__ float g_wdense_t[(size_t)Hq * Hq];
__device__ float g_wfc_t   [(size_t)FF * Hq];
__device__ float g_wout_t  [(size_t)Hq * FF];

// ---------------------------------------------------------------------------
// Weight transpose + tf32 round: Wt[n,k] = rna_tf32(W[k,n])
// ---------------------------------------------------------------------------
__global__ void __launch_bounds__(256)
transpose_rna_kernel(const float* __restrict__ W, float* __restrict__ Wt, int Kd, int Nd)
{
    __shared__ float tile[32][33];
    int n0 = blockIdx.x * 32, k0 = blockIdx.y * 32;
    int tx = threadIdx.x & 31, ty = threadIdx.x >> 5;
    #pragma unroll
    for (int r = 0; r < 32; r += 8)
        tile[ty + r][tx] = W[(size_t)(k0 + ty + r) * Nd + n0 + tx];
    __syncthreads();
    #pragma unroll
    for (int r = 0; r < 32; r += 8)
        Wt[(size_t)(n0 + ty + r) * Kd + k0 + tx] = tf32r(tile[tx][ty + r]);
}

// ---------------------------------------------------------------------------
// Dual LayerNorm (tf32-rounds outputs, which feed MMAs)
// ---------------------------------------------------------------------------
__global__ void __launch_bounds__(256)
ln_dual_kernel(const float* __restrict__ x,
               const float* __restrict__ s1, const float* __restrict__ b1,
               const float* __restrict__ s2, const float* __restrict__ b2,
               float* __restrict__ o1, float* __restrict__ o2)
{
    int row = blockIdx.x;
    const float4* xr = (const float4*)(x + (size_t)row * Hq);

    float sum = 0.f, sq = 0.f;
    for (int i = threadIdx.x; i < Hq / 4; i += 256) {
        float4 v = xr[i];
        sum += v.x + v.y + v.z + v.w;
        sq  += v.x*v.x + v.y*v.y + v.z*v.z + v.w*v.w;
    }
    #pragma unroll
    for (int o = 16; o; o >>= 1) {
        sum += __shfl_xor_sync(0xFFFFFFFFu, sum, o);
        sq  += __shfl_xor_sync(0xFFFFFFFFu, sq,  o);
    }
    __shared__ float wsum[8], wsq[8];
    int w = threadIdx.x >> 5, l = threadIdx.x & 31;
    if (l == 0) { wsum[w] = sum; wsq[w] = sq; }
    __syncthreads();
    sum = 0.f; sq = 0.f;
    #pragma unroll
    for (int i = 0; i < 8; i++) { sum += wsum[i]; sq += wsq[i]; }

    float mean = sum * (1.0f / Hq);
    float var  = sq  * (1.0f / Hq) - mean * mean;
    float rstd = rsqrtf(var + EPS);

    const float4* s1r = (const float4*)s1;
    const float4* b1r = (const float4*)b1;
    const float4* s2r = (const float4*)s2;
    const float4* b2r = (const float4*)b2;
    float4* o1r = (float4*)(o1 + (size_t)row * Hq);
    float4* o2r = (float4*)(o2 + (size_t)row * Hq);

    for (int i = threadIdx.x; i < Hq / 4; i += 256) {
        float4 v = xr[i];
        float4 a = s1r[i], c = b1r[i], d = s2r[i], e = b2r[i];
        float nx = (v.x - mean) * rstd;
        float ny = (v.y - mean) * rstd;
        float nz = (v.z - mean) * rstd;
        float nw = (v.w - mean) * rstd;
        o1r[i] = make_float4(tf32r(nx*a.x + c.x), tf32r(ny*a.y + c.y),
                             tf32r(nz*a.z + c.z), tf32r(nw*a.w + c.w));
        o2r[i] = make_float4(tf32r(nx*d.x + e.x), tf32r(ny*d.y + e.y),
                             tf32r(nz*d.z + e.z), tf32r(nw*d.w + e.w));
    }
}

// ---------------------------------------------------------------------------
// tf32 mma.sync GEMM: C[M,N] = A[M,K] @ Bt[N,K]^T
// 128x128x16 CTA tile, 8 warps (4m x 2n), warp tile 32x64 (2x8 m16n8k8).
// cp.async double-buffered smem, 20-float row stride (conflict-free).
// EPI: 0 none, 1 exact GELU (+tf32 round), 2 +R1+R2
// ---------------------------------------------------------------------------
#define SROW 20

__device__ __forceinline__ void mma_tf32(float* c, uint32_t a0, uint32_t a1,
                                         uint32_t a2, uint32_t a3,
                                         uint32_t b0, uint32_t b1)
{
    asm volatile(
        "mma.sync.aligned.m16n8k8.row.col.f32.tf32.tf32.f32 "
        "{%0,%1,%2,%3}, {%4,%5,%6,%7}, {%8,%9}, {%0,%1,%2,%3};"
        : "+f"(c[0]), "+f"(c[1]), "+f"(c[2]), "+f"(c[3])
        : "r"(a0), "r"(a1), "r"(a2), "r"(a3), "r"(b0), "r"(b1));
}

template <int EPI>
__global__ void __launch_bounds__(256)
mma_gemm_kernel(const float* __restrict__ A, const float* __restrict__ Bt,
                float* __restrict__ C, int K, int N,
                const float* __restrict__ R1, const float* __restrict__ R2)
{
    __shared__ float As[2][128 * SROW];
    __shared__ float Bs[2][128 * SROW];

    int tid = threadIdx.x;
    int lane = tid & 31;
    int wid = tid >> 5;
    int wm = (wid & 3) * 32;
    int wn = (wid >> 2) * 64;
    int lr = lane >> 2;          // 0..7
    int lc = lane & 3;           // 0..3
    int m0 = blockIdx.x * 128;
    int n0 = blockIdx.y * 128;

    const float* Ag = A  + (size_t)m0 * K;
    const float* Bg = Bt + (size_t)n0 * K;

    float acc[2][8][4];
    #pragma unroll
    for (int i = 0; i < 2; i++)
        #pragma unroll
        for (int j = 0; j < 8; j++)
            #pragma unroll
            for (int q = 0; q < 4; q++) acc[i][j][q] = 0.f;

    int row = tid >> 2;
    int c4  = (tid & 3) * 4;

    // prologue: fill buffer 0
    {
        #pragma unroll
        for (int j = 0; j < 2; j++) {
            int r = row + j * 64;
            CP_ASYNC16(smem_u32(&As[0][r * SROW + c4]), Ag + (size_t)r * K + c4);
            CP_ASYNC16(smem_u32(&Bs[0][r * SROW + c4]), Bg + (size_t)r * K + c4);
        }
        CP_COMMIT();
    }

    const int NC = K / 16;
    for (int c = 0; c < NC; c++) {
        int b = c & 1;
        if (c + 1 < NC) {
            int k0 = (c + 1) * 16;
            #pragma unroll
            for (int j = 0; j < 2; j++) {
                int r = row + j * 64;
                CP_ASYNC16(smem_u32(&As[b ^ 1][r * SROW + c4]), Ag + (size_t)r * K + k0 + c4);
                CP_ASYNC16(smem_u32(&Bs[b ^ 1][r * SROW + c4]), Bg + (size_t)r * K + k0 + c4);
            }
            CP_COMMIT();
            asm volatile("cp.async.wait_group 1;" ::: "memory");
        } else {
            asm volatile("cp.async.wait_group 0;" ::: "memory");
        }
        __syncthreads();

        #pragma unroll
        for (int ks = 0; ks < 2; ks++) {
            int ko = ks * 8;
            uint32_t af[2][4];
            #pragma unroll
            for (int i = 0; i < 2; i++) {
                const float* ab = &As[b][(wm + i * 16 + lr) * SROW + ko + lc];
                af[i][0] = __float_as_uint(ab[0]);
                af[i][1] = __float_as_uint(ab[8 * SROW]);
                af[i][2] = __float_as_uint(ab[4]);
                af[i][3] = __float_as_uint(ab[8 * SROW + 4]);
            }
            #pragma unroll
            for (int j = 0; j < 8; j++) {
                const float* bb = &Bs[b][(wn + j * 8 + lr) * SROW + ko + lc];
                uint32_t b0 = __float_as_uint(bb[0]);
                uint32_t b1 = __float_as_uint(bb[4]);
                mma_tf32(acc[0][j], af[0][0], af[0][1], af[0][2], af[0][3], b0, b1);
                mma_tf32(acc[1][j], af[1][0], af[1][1], af[1][2], af[1][3], b0, b1);
            }
        }
        __syncthreads();   // protect buffer b^1... (next iter's cp.async targets buffer b)
    }

    // epilogue
    #pragma unroll
    for (int i = 0; i < 2; i++) {
        #pragma unroll
        for (int j = 0; j < 8; j++) {
            int r0 = m0 + wm + i * 16 + lr;
            int cc = n0 + wn + j * 8 + lc * 2;
            float x0 = acc[i][j][0], x1 = acc[i][j][1];
            float x2 = acc[i][j][2], x3 = acc[i][j][3];
            if (EPI == 1) {
                x0 = tf32r(gelu_exact(x0)); x1 = tf32r(gelu_exact(x1));
                x2 = tf32r(gelu_exact(x2)); x3 = tf32r(gelu_exact(x3));
            }
            if (EPI == 2) {
                size_t i0 = (size_t)r0 * N + cc;
                size_t i1 = (size_t)(r0 + 8) * N + cc;
                float2 a0 = *(const float2*)(R1 + i0);
                float2 a1 = *(const float2*)(R1 + i1);
                float2 d0 = *(const float2*)(R2 + i0);
                float2 d1 = *(const float2*)(R2 + i1);
                x0 += a0.x + d0.x; x1 += a0.y + d0.y;
                x2 += a1.x + d1.x; x3 += a1.y + d1.y;
            }
            *(float2*)(C + (size_t)r0 * N + cc)       = make_float2(x0, x1);
            *(float2*)(C + (size_t)(r0 + 8) * N + cc) = make_float2(x2, x3);
        }
    }
}

// ---------------------------------------------------------------------------
// RoPE + head split
// ---------------------------------------------------------------------------
__global__ void __launch_bounds__(128)
rope_kernel(const float* __restrict__ qkv,
            const float* __restrict__ sint, const float* __restrict__ cost,
            const int* __restrict__ pos_ids,
            float* __restrict__ Qo, float* __restrict__ Ko, float* __restrict__ Vo)
{
    int d = threadIdx.x;
    int idx = blockIdx.x;
    int kvh = idx % NKV; idx /= NKV;
    int s = idx % Sq;
    int b = idx / Sq;

    int pos = pos_ids[b * Sq + s];
    float sn = sint[pos * HD + d];
    float cs = cost[pos * HD + d];
    int dro = (d < 64) ? (d + 64) : (d - 64);
    float sgn = (d < 64) ? -1.f : 1.f;

    const float* base = qkv + (size_t)(b * Sq + s) * QKVW + kvh * (Gq + 2) * HD;

    float kx = base[Gq * HD + d];
    float ko = base[Gq * HD + dro];
    size_t kvidx = ((size_t)(b * NKV + kvh) * Sq + s) * HD + d;
    Ko[kvidx] = kx * cs + sgn * ko * sn;
    Vo[kvidx] = base[(Gq + 1) * HD + d];

    #pragma unroll
    for (int g = 0; g < Gq; g++) {
        int h = kvh * Gq + g;
        float qx = base[g * HD + d];
        float qo = base[g * HD + dro];
        Qo[((size_t)(b * NH + h) * Sq + s) * HD + d] = qx * cs + sgn * qo * sn;
    }
}

// ---------------------------------------------------------------------------
// Flash attention (fp32; ctx tf32-rounded for the dense MMA that follows)
// ---------------------------------------------------------------------------
#define QT 64
#define KT 64
#define DPAD 132
#define SPAD 66
#define ATTN_SMEM ((3 * QT * DPAD + QT * SPAD + 3 * QT) * 4)

__global__ void __launch_bounds__(256)
attn_kernel(const float* __restrict__ Q, const float* __restrict__ Kg,
            const float* __restrict__ Vg, const int* __restrict__ amask,
            float* __restrict__ ctx)
{
    extern __shared__ float sm[];
    float* Qs   = sm;
    float* Ks   = Qs + QT * DPAD;
    float* Vs   = Ks + KT * DPAD;
    float* Ss   = Vs + KT * DPAD;
    float* rowm = Ss + QT * SPAD;
    float* rowl = rowm + QT;
    float* rowc = rowl + QT;

    int t  = threadIdx.x;
    int q0 = blockIdx.x * QT;
    int h  = blockIdx.y;
    int b  = blockIdx.z;
    int kv = h >> 2;

    const float* Qb = Q  + ((size_t)(b * NH  + h ) * Sq + q0) * HD;
    const float* Kb = Kg + ((size_t)(b * NKV + kv) * Sq) * HD;
    const float* Vb = Vg + ((size_t)(b * NKV + kv) * Sq) * HD;

    for (int i = t; i < QT * (HD / 4); i += 256) {
        int r = i >> 5;
        int c = (i & 31) * 4;
        *(float4*)&Qs[r * DPAD + c] = *(const float4*)(Qb + (size_t)r * HD + c);
    }
    if (t < QT) { rowm[t] = -1e30f; rowl[t] = 0.f; }

    float4 o[8];
    #pragma unroll
    for (int i = 0; i < 8; i++) o[i] = make_float4(0.f, 0.f, 0.f, 0.f);

    int cg = t & 31;
    int rb = t >> 5;
    int qr = t >> 2;
    int kb = t & 3;

    __syncthreads();

    int kend = q0 + QT;
    for (int k0 = 0; k0 < kend; k0 += KT) {
        for (int i = t; i < KT * (HD / 4); i += 256) {
            int r = i >> 5;
            int c = (i & 31) * 4;
            *(float4*)&Ks[r * DPAD + c] = *(const float4*)(Kb + (size_t)(k0 + r) * HD + c);
            *(float4*)&Vs[r * DPAD + c] = *(const float4*)(Vb + (size_t)(k0 + r) * HD + c);
        }
        __syncthreads();

        float acc[16];
        #pragma unroll
        for (int j = 0; j < 16; j++) acc[j] = 0.f;
        const float4* qrow = (const float4*)&Qs[qr * DPAD];
        for (int d4 = 0; d4 < 32; d4++) {
            float4 qv = qrow[d4];
            #pragma unroll
            for (int j = 0; j < 16; j++) {
                float4 kvv = *(const float4*)&Ks[(kb + 4 * j) * DPAD + d4 * 4];
                acc[j] += qv.x * kvv.x + qv.y * kvv.y + qv.z * kvv.z + qv.w * kvv.w;
            }
        }
        int qg = q0 + qr;
        #pragma unroll
        for (int j = 0; j < 16; j++) {
            int kk = kb + 4 * j;
            int kg = k0 + kk;
            bool valid = (kg <= qg) && (amask[b * Sq + kg] > 0);
            Ss[qr * SPAD + kk] = valid ? acc[j] * ATTN_SCALE : -1e30f;
        }
        __syncthreads();

        if (t < QT) {
            float m_old = rowm[t];
            float m = m_old;
            #pragma unroll 8
            for (int k = 0; k < KT; k++) m = fmaxf(m, Ss[t * SPAD + k]);
            float cfac = __expf(m_old - m);
            float lsum = 0.f;
            #pragma unroll 8
            for (int k = 0; k < KT; k++) {
                float p = __expf(Ss[t * SPAD + k] - m);
                Ss[t * SPAD + k] = p;
                lsum += p;
            }
            rowm[t] = m;
            rowl[t] = rowl[t] * cfac + lsum;
            rowc[t] = cfac;
        }
        __syncthreads();

        #pragma unroll
        for (int i = 0; i < 8; i++) {
            int r = rb + 8 * i;
            float cfac = rowc[r];
            float4 ov = o[i];
            ov.x *= cfac; ov.y *= cfac; ov.z *= cfac; ov.w *= cfac;
            const float* srow = &Ss[r * SPAD];
            #pragma unroll 4
            for (int k = 0; k < KT; k++) {
                float p = srow[k];
                float4 vv = *(const float4*)&Vs[k * DPAD + cg * 4];
                ov.x += p * vv.x; ov.y += p * vv.y;
                ov.z += p * vv.z; ov.w += p * vv.w;
            }
            o[i] = ov;
        }
        __syncthreads();
    }

    #pragma unroll
    for (int i = 0; i < 8; i++) {
        int r = rb + 8 * i;
        float inv = 1.f / rowl[r];
        float4 ov = o[i];
        size_t idx = ((size_t)(b * Sq + q0 + r)) * Hq + h * HD + cg * 4;
        *(float4*)&ctx[idx] = make_float4(tf32r(ov.x * inv), tf32r(ov.y * inv),
                                          tf32r(ov.z * inv), tf32r(ov.w * inv));
    }
}

// ---------------------------------------------------------------------------
// Launch
// ---------------------------------------------------------------------------
extern "C" void kernel_launch(void* const* d_in, const int* in_sizes, int n_in,
                              void* d_out, int out_size)
{
    const float* hidden  = (const float*)d_in[0];
    const float* w_qkv   = (const float*)d_in[1];
    const float* w_dense = (const float*)d_in[2];
    const float* ln_a_s  = (const float*)d_in[3];
    const float* ln_a_b  = (const float*)d_in[4];
    const float* ln_m_s  = (const float*)d_in[5];
    const float* ln_m_b  = (const float*)d_in[6];
    const float* w_fc    = (const float*)d_in[7];
    const float* w_out   = (const float*)d_in[8];
    const float* sin_tab = (const float*)d_in[9];
    const float* cos_tab = (const float*)d_in[10];
    const int*   amask   = (const int*)d_in[11];
    const int*   pos_ids = (const int*)d_in[12];
    float* out = (float*)d_out;

    float *p_attn_in, *p_mlp_in, *p_qkv, *p_q, *p_k, *p_v, *p_ctx, *p_attn_out, *p_fc;
    float *p_wqkv, *p_wdense, *p_wfc, *p_wout;
    cudaGetSymbolAddress((void**)&p_attn_in,  g_attn_in);
    cudaGetSymbolAddress((void**)&p_mlp_in,   g_mlp_in);
    cudaGetSymbolAddress((void**)&p_qkv,      g_qkv);
    cudaGetSymbolAddress((void**)&p_q,        g_q);
    cudaGetSymbolAddress((void**)&p_k,        g_k);
    cudaGetSymbolAddress((void**)&p_v,        g_v);
    cudaGetSymbolAddress((void**)&p_ctx,      g_ctx);
    cudaGetSymbolAddress((void**)&p_attn_out, g_attn_out);
    cudaGetSymbolAddress((void**)&p_fc,       g_fc);
    cudaGetSymbolAddress((void**)&p_wqkv,     g_wqkv_t);
    cudaGetSymbolAddress((void**)&p_wdense,   g_wdense_t);
    cudaGetSymbolAddress((void**)&p_wfc,      g_wfc_t);
    cudaGetSymbolAddress((void**)&p_wout,     g_wout_t);

    cudaFuncSetAttribute(attn_kernel, cudaFuncAttributeMaxDynamicSharedMemorySize, ATTN_SMEM);

    // 0. transpose + tf32-round weights into [N,K]
    transpose_rna_kernel<<<dim3(QKVW/32, Hq/32), 256>>>(w_qkv,   p_wqkv,   Hq, QKVW);
    transpose_rna_kernel<<<dim3(Hq/32,   Hq/32), 256>>>(w_dense, p_wdense, Hq, Hq);
    transpose_rna_kernel<<<dim3(FF/32,   Hq/32), 256>>>(w_fc,    p_wfc,    Hq, FF);
    transpose_rna_kernel<<<dim3(Hq/32,   FF/32), 256>>>(w_out,   p_wout,   FF, Hq);

    // 1. parallel layernorms (tf32-rounded outputs)
    ln_dual_kernel<<<Mrows, 256>>>(hidden, ln_a_s, ln_a_b, ln_m_s, ln_m_b,
                                   p_attn_in, p_mlp_in);

    // 2. qkv projection
    mma_gemm_kernel<0><<<dim3(Mrows/128, QKVW/128), 256>>>(
        p_attn_in, p_wqkv, p_qkv, Hq, QKVW, nullptr, nullptr);

    // 3. rope + head split
    rope_kernel<<<Bq * Sq * NKV, 128>>>(p_qkv, sin_tab, cos_tab, pos_ids,
                                        p_q, p_k, p_v);

    // 4. attention
    attn_kernel<<<dim3(Sq / QT, NH, Bq), 256, ATTN_SMEM>>>(
        p_q, p_k, p_v, amask, p_ctx);

    // 5. dense projection
    mma_gemm_kernel<0><<<dim3(Mrows/128, Hq/128), 256>>>(
        p_ctx, p_wdense, p_attn_out, Hq, Hq, nullptr, nullptr);

    // 6. MLP fc + exact GELU
    mma_gemm_kernel<1><<<dim3(Mrows/128, FF/128), 256>>>(
        p_mlp_in, p_wfc, p_fc, Hq, FF, nullptr, nullptr);

    // 7. MLP out + parallel residual -> d_out
    mma_gemm_kernel<2><<<dim3(Mrows/128, Hq/128), 256>>>(
        p_fc, p_wout, out, FF, Hq, hidden, p_attn_out);
}

// round 4
// speedup vs baseline: 3.0030x; 1.0449x over previous
#include <cuda_runtime.h>
#include <cuda_bf16.h>
#include <math.h>
#include <stdint.h>

// ---------------------------------------------------------------------------
// Problem constants
// ---------------------------------------------------------------------------
#define Bq   2
#define Sq   1024
#define Hq   4096
#define NH   32
#define NKV  8
#define HD   128
#define Gq   4
#define QKVW 6144
#define FF   16384
#define Mrows (Bq * Sq)
#define EPS  1e-5f
#define ATTN_SCALE 0.08838834764831845f

// ---------------------------------------------------------------------------
// Helpers
// ---------------------------------------------------------------------------
__device__ __forceinline__ uint32_t smem_u32(const void* p) {
    uint32_t a;
    asm("{ .reg .u64 t; cvta.to.shared.u64 t, %1; cvt.u32.u64 %0, t; }" : "=r"(a) : "l"(p));
    return a;
}
#define CP_ASYNC16(dst, src) \
    asm volatile("cp.async.cg.shared.global [%0], [%1], 16;" :: "r"(dst), "l"(src) : "memory")
#define CP_COMMIT() asm volatile("cp.async.commit_group;" ::: "memory")

__device__ __forceinline__ float tf32r(float x) {
    uint32_t u;
    asm("cvt.rna.tf32.f32 %0, %1;" : "=r"(u) : "f"(x));
    return __uint_as_float(u);
}
__device__ __forceinline__ float gelu_exact(float x) {
    return 0.5f * x * (1.0f + erff(x * 0.7071067811865475f));
}

__device__ __forceinline__ void mma_tf32(float* c, uint32_t a0, uint32_t a1,
                                         uint32_t a2, uint32_t a3,
                                         uint32_t b0, uint32_t b1)
{
    asm volatile(
        "mma.sync.aligned.m16n8k8.row.col.f32.tf32.tf32.f32 "
        "{%0,%1,%2,%3}, {%4,%5,%6,%7}, {%8,%9}, {%0,%1,%2,%3};"
        : "+f"(c[0]), "+f"(c[1]), "+f"(c[2]), "+f"(c[3])
        : "r"(a0), "r"(a1), "r"(a2), "r"(a3), "r"(b0), "r"(b1));
}

// ---------------------------------------------------------------------------
// Scratch (device globals)
// ---------------------------------------------------------------------------
__device__ float g_attn_in [Mrows * Hq];
__device__ float g_mlp_in  [Mrows * Hq];
__device__ float g_qkv     [Mrows * QKVW];
__device__ float g_q       [(size_t)Bq * NH  * Sq * HD];
__device__ float g_k       [(size_t)Bq * NKV * Sq * HD];
__device__ float g_v       [(size_t)Bq * NKV * Sq * HD];
__device__ float g_ctx     [Mrows * Hq];
__device__ float g_attn_out[Mrows * Hq];
__device__ float g_fc      [(size_t)Mrows * FF];
__device__ float g_wqkv_t  [(size_t)QKVW * Hq];
__device__ float g_wdense_t[(size_t)Hq * Hq];
__device__ float g_wfc_t   [(size_t)FF * Hq];
__device__ float g_wout_t  [(size_t)Hq * FF];

// ---------------------------------------------------------------------------
// Weight transpose + tf32 round: Wt[n,k] = rna_tf32(W[k,n])
// ---------------------------------------------------------------------------
__global__ void __launch_bounds__(256)
transpose_rna_kernel(const float* __restrict__ W, float* __restrict__ Wt, int Kd, int Nd)
{
    __shared__ float tile[32][33];
    int n0 = blockIdx.x * 32, k0 = blockIdx.y * 32;
    int tx = threadIdx.x & 31, ty = threadIdx.x >> 5;
    #pragma unroll
    for (int r = 0; r < 32; r += 8)
        tile[ty + r][tx] = W[(size_t)(k0 + ty + r) * Nd + n0 + tx];
    __syncthreads();
    #pragma unroll
    for (int r = 0; r < 32; r += 8)
        Wt[(size_t)(n0 + ty + r) * Kd + k0 + tx] = tf32r(tile[tx][ty + r]);
}

// ---------------------------------------------------------------------------
// Dual LayerNorm (tf32-rounds outputs, which feed MMAs)
// ---------------------------------------------------------------------------
__global__ void __launch_bounds__(256)
ln_dual_kernel(const float* __restrict__ x,
               const float* __restrict__ s1, const float* __restrict__ b1,
               const float* __restrict__ s2, const float* __restrict__ b2,
               float* __restrict__ o1, float* __restrict__ o2)
{
    int row = blockIdx.x;
    const float4* xr = (const float4*)(x + (size_t)row * Hq);

    float sum = 0.f, sq = 0.f;
    for (int i = threadIdx.x; i < Hq / 4; i += 256) {
        float4 v = xr[i];
        sum += v.x + v.y + v.z + v.w;
        sq  += v.x*v.x + v.y*v.y + v.z*v.z + v.w*v.w;
    }
    #pragma unroll
    for (int o = 16; o; o >>= 1) {
        sum += __shfl_xor_sync(0xFFFFFFFFu, sum, o);
        sq  += __shfl_xor_sync(0xFFFFFFFFu, sq,  o);
    }
    __shared__ float wsum[8], wsq[8];
    int w = threadIdx.x >> 5, l = threadIdx.x & 31;
    if (l == 0) { wsum[w] = sum; wsq[w] = sq; }
    __syncthreads();
    sum = 0.f; sq = 0.f;
    #pragma unroll
    for (int i = 0; i < 8; i++) { sum += wsum[i]; sq += wsq[i]; }

    float mean = sum * (1.0f / Hq);
    float var  = sq  * (1.0f / Hq) - mean * mean;
    float rstd = rsqrtf(var + EPS);

    const float4* s1r = (const float4*)s1;
    const float4* b1r = (const float4*)b1;
    const float4* s2r = (const float4*)s2;
    const float4* b2r = (const float4*)b2;
    float4* o1r = (float4*)(o1 + (size_t)row * Hq);
    float4* o2r = (float4*)(o2 + (size_t)row * Hq);

    for (int i = threadIdx.x; i < Hq / 4; i += 256) {
        float4 v = xr[i];
        float4 a = s1r[i], c = b1r[i], d = s2r[i], e = b2r[i];
        float nx = (v.x - mean) * rstd;
        float ny = (v.y - mean) * rstd;
        float nz = (v.z - mean) * rstd;
        float nw = (v.w - mean) * rstd;
        o1r[i] = make_float4(tf32r(nx*a.x + c.x), tf32r(ny*a.y + c.y),
                             tf32r(nz*a.z + c.z), tf32r(nw*a.w + c.w));
        o2r[i] = make_float4(tf32r(nx*d.x + e.x), tf32r(ny*d.y + e.y),
                             tf32r(nz*d.z + e.z), tf32r(nw*d.w + e.w));
    }
}

// ---------------------------------------------------------------------------
// tf32 mma.sync GEMM: C[M,N] = A[M,K] @ Bt[N,K]^T
// 256x128x16 CTA tile, 8 warps (4m x 2n), warp tile 64x64 (4x8 m16n8k8).
// 4-stage cp.async ring, ONE __syncthreads per chunk.
// EPI: 0 none, 1 exact GELU (+tf32 round), 2 +R1+R2
// ---------------------------------------------------------------------------
#define SROW 20
#define GSTG 4
#define ASZ  (256 * SROW)
#define BSZ  (128 * SROW)
#define GEMM_SMEM (GSTG * (ASZ + BSZ) * 4)   // 122880 bytes

__device__ __forceinline__ void g_load(const float* __restrict__ Ag,
                                       const float* __restrict__ Bg, int K,
                                       float* As, float* Bs, int k0, int tid)
{
    int c4 = (tid & 3) * 4;
    int rA = tid >> 2;                  // 0..63
    #pragma unroll
    for (int j = 0; j < 4; j++) {
        int r = rA + j * 64;
        CP_ASYNC16(smem_u32(&As[r * SROW + c4]), Ag + (size_t)r * K + k0 + c4);
    }
    #pragma unroll
    for (int j = 0; j < 2; j++) {
        int r = rA + j * 64;
        CP_ASYNC16(smem_u32(&Bs[r * SROW + c4]), Bg + (size_t)r * K + k0 + c4);
    }
    CP_COMMIT();
}

template <int EPI>
__global__ void __launch_bounds__(256, 1)
mma_gemm_kernel(const float* __restrict__ A, const float* __restrict__ Bt,
                float* __restrict__ C, int K, int N,
                const float* __restrict__ R1, const float* __restrict__ R2)
{
    extern __shared__ float gsm[];
    float* AsB = gsm;                    // [GSTG][ASZ]
    float* BsB = gsm + GSTG * ASZ;       // [GSTG][BSZ]

    int tid = threadIdx.x;
    int lane = tid & 31;
    int wid = tid >> 5;
    int wm = (wid & 3) * 64;
    int wn = (wid >> 2) * 64;
    int lr = lane >> 2;
    int lc = lane & 3;
    int m0 = blockIdx.x * 256;
    int n0 = blockIdx.y * 128;

    const float* Ag = A  + (size_t)m0 * K;
    const float* Bg = Bt + (size_t)n0 * K;

    float acc[4][8][4];
    #pragma unroll
    for (int i = 0; i < 4; i++)
        #pragma unroll
        for (int j = 0; j < 8; j++)
            #pragma unroll
            for (int q = 0; q < 4; q++) acc[i][j][q] = 0.f;

    const int NC = K / 16;
    g_load(Ag, Bg, K, AsB + 0 * ASZ, BsB + 0 * BSZ,  0, tid);
    g_load(Ag, Bg, K, AsB + 1 * ASZ, BsB + 1 * BSZ, 16, tid);
    g_load(Ag, Bg, K, AsB + 2 * ASZ, BsB + 2 * BSZ, 32, tid);

    for (int c = 0; c < NC; c++) {
        if (c + 2 < NC) asm volatile("cp.async.wait_group 2;" ::: "memory");
        else            asm volatile("cp.async.wait_group 0;" ::: "memory");
        __syncthreads();

        if (c + 3 < NC)
            g_load(Ag, Bg, K, AsB + ((c + 3) & 3) * ASZ, BsB + ((c + 3) & 3) * BSZ,
                   (c + 3) * 16, tid);

        const float* Ast = AsB + (c & 3) * ASZ;
        const float* Bst = BsB + (c & 3) * BSZ;

        #pragma unroll
        for (int ks = 0; ks < 2; ks++) {
            int ko = ks * 8;
            uint32_t af[4][4];
            #pragma unroll
            for (int i = 0; i < 4; i++) {
                const float* ab = &Ast[(wm + i * 16 + lr) * SROW + ko + lc];
                af[i][0] = __float_as_uint(ab[0]);
                af[i][1] = __float_as_uint(ab[8 * SROW]);
                af[i][2] = __float_as_uint(ab[4]);
                af[i][3] = __float_as_uint(ab[8 * SROW + 4]);
            }
            #pragma unroll
            for (int j = 0; j < 8; j++) {
                const float* bb = &Bst[(wn + j * 8 + lr) * SROW + ko + lc];
                uint32_t b0 = __float_as_uint(bb[0]);
                uint32_t b1 = __float_as_uint(bb[4]);
                #pragma unroll
                for (int i = 0; i < 4; i++)
                    mma_tf32(acc[i][j], af[i][0], af[i][1], af[i][2], af[i][3], b0, b1);
            }
        }
    }

    // epilogue
    #pragma unroll
    for (int i = 0; i < 4; i++) {
        #pragma unroll
        for (int j = 0; j < 8; j++) {
            int r0 = m0 + wm + i * 16 + lr;
            int cc = n0 + wn + j * 8 + lc * 2;
            float x0 = acc[i][j][0], x1 = acc[i][j][1];
            float x2 = acc[i][j][2], x3 = acc[i][j][3];
            if (EPI == 1) {
                x0 = tf32r(gelu_exact(x0)); x1 = tf32r(gelu_exact(x1));
                x2 = tf32r(gelu_exact(x2)); x3 = tf32r(gelu_exact(x3));
            }
            if (EPI == 2) {
                size_t i0 = (size_t)r0 * N + cc;
                size_t i1 = (size_t)(r0 + 8) * N + cc;
                float2 a0 = *(const float2*)(R1 + i0);
                float2 a1 = *(const float2*)(R1 + i1);
                float2 d0 = *(const float2*)(R2 + i0);
                float2 d1 = *(const float2*)(R2 + i1);
                x0 += a0.x + d0.x; x1 += a0.y + d0.y;
                x2 += a1.x + d1.x; x3 += a1.y + d1.y;
            }
            *(float2*)(C + (size_t)r0 * N + cc)       = make_float2(x0, x1);
            *(float2*)(C + (size_t)(r0 + 8) * N + cc) = make_float2(x2, x3);
        }
    }
}

// ---------------------------------------------------------------------------
// RoPE + head split
// ---------------------------------------------------------------------------
__global__ void __launch_bounds__(128)
rope_kernel(const float* __restrict__ qkv,
            const float* __restrict__ sint, const float* __restrict__ cost,
            const int* __restrict__ pos_ids,
            float* __restrict__ Qo, float* __restrict__ Ko, float* __restrict__ Vo)
{
    int d = threadIdx.x;
    int idx = blockIdx.x;
    int kvh = idx % NKV; idx /= NKV;
    int s = idx % Sq;
    int b = idx / Sq;

    int pos = pos_ids[b * Sq + s];
    float sn = sint[pos * HD + d];
    float cs = cost[pos * HD + d];
    int dro = (d < 64) ? (d + 64) : (d - 64);
    float sgn = (d < 64) ? -1.f : 1.f;

    const float* base = qkv + (size_t)(b * Sq + s) * QKVW + kvh * (Gq + 2) * HD;

    float kx = base[Gq * HD + d];
    float ko = base[Gq * HD + dro];
    size_t kvidx = ((size_t)(b * NKV + kvh) * Sq + s) * HD + d;
    Ko[kvidx] = kx * cs + sgn * ko * sn;
    Vo[kvidx] = base[(Gq + 1) * HD + d];

    #pragma unroll
    for (int g = 0; g < Gq; g++) {
        int h = kvh * Gq + g;
        float qx = base[g * HD + d];
        float qo = base[g * HD + dro];
        Qo[((size_t)(b * NH + h) * Sq + s) * HD + d] = qx * cs + sgn * qo * sn;
    }
}

// ---------------------------------------------------------------------------
// Flash attention (fp32; parallel softmax, 4 threads/row)
// ---------------------------------------------------------------------------
#define QT 64
#define KT 64
#define DPAD 132
#define SPAD 66
#define ATTN_SMEM ((3 * QT * DPAD + QT * SPAD + 3 * QT) * 4)

__global__ void __launch_bounds__(256)
attn_kernel(const float* __restrict__ Q, const float* __restrict__ Kg,
            const float* __restrict__ Vg, const int* __restrict__ amask,
            float* __restrict__ ctx)
{
    extern __shared__ float sm[];
    float* Qs   = sm;
    float* Ks   = Qs + QT * DPAD;
    float* Vs   = Ks + KT * DPAD;
    float* Ss   = Vs + KT * DPAD;
    float* rowm = Ss + QT * SPAD;
    float* rowl = rowm + QT;
    float* rowc = rowl + QT;

    int t  = threadIdx.x;
    int q0 = blockIdx.x * QT;
    int h  = blockIdx.y;
    int b  = blockIdx.z;
    int kv = h >> 2;

    const float* Qb = Q  + ((size_t)(b * NH  + h ) * Sq + q0) * HD;
    const float* Kb = Kg + ((size_t)(b * NKV + kv) * Sq) * HD;
    const float* Vb = Vg + ((size_t)(b * NKV + kv) * Sq) * HD;

    for (int i = t; i < QT * (HD / 4); i += 256) {
        int r = i >> 5;
        int c = (i & 31) * 4;
        *(float4*)&Qs[r * DPAD + c] = *(const float4*)(Qb + (size_t)r * HD + c);
    }
    if (t < QT) { rowm[t] = -1e30f; rowl[t] = 0.f; }

    float4 o[8];
    #pragma unroll
    for (int i = 0; i < 8; i++) o[i] = make_float4(0.f, 0.f, 0.f, 0.f);

    int cg = t & 31;
    int rb = t >> 5;
    int qr = t >> 2;
    int kb = t & 3;

    __syncthreads();

    int kend = q0 + QT;
    for (int k0 = 0; k0 < kend; k0 += KT) {
        for (int i = t; i < KT * (HD / 4); i += 256) {
            int r = i >> 5;
            int c = (i & 31) * 4;
            *(float4*)&Ks[r * DPAD + c] = *(const float4*)(Kb + (size_t)(k0 + r) * HD + c);
            *(float4*)&Vs[r * DPAD + c] = *(const float4*)(Vb + (size_t)(k0 + r) * HD + c);
        }
        __syncthreads();

        // scores
        float acc[16];
        #pragma unroll
        for (int j = 0; j < 16; j++) acc[j] = 0.f;
        const float4* qrow = (const float4*)&Qs[qr * DPAD];
        for (int d4 = 0; d4 < 32; d4++) {
            float4 qv = qrow[d4];
            #pragma unroll
            for (int j = 0; j < 16; j++) {
                float4 kvv = *(const float4*)&Ks[(kb + 4 * j) * DPAD + d4 * 4];
                acc[j] += qv.x * kvv.x + qv.y * kvv.y + qv.z * kvv.z + qv.w * kvv.w;
            }
        }
        int qg = q0 + qr;
        #pragma unroll
        for (int j = 0; j < 16; j++) {
            int kk = kb + 4 * j;
            int kg = k0 + kk;
            bool valid = (kg <= qg) && (amask[b * Sq + kg] > 0);
            Ss[qr * SPAD + kk] = valid ? acc[j] * ATTN_SCALE : -1e30f;
        }
        __syncthreads();

        // online softmax: 4 threads per row
        {
            int row = t >> 2, seg = t & 3;
            float* srow = &Ss[row * SPAD];
            float m_old = rowm[row];
            float m = -1e30f;
            #pragma unroll
            for (int k = 0; k < 16; k++) m = fmaxf(m, srow[seg * 16 + k]);
            m = fmaxf(m, __shfl_xor_sync(0xFFFFFFFFu, m, 1));
            m = fmaxf(m, __shfl_xor_sync(0xFFFFFFFFu, m, 2));
            float mn = fmaxf(m_old, m);
            float lsum = 0.f;
            #pragma unroll
            for (int k = 0; k < 16; k++) {
                float p = __expf(srow[seg * 16 + k] - mn);
                srow[seg * 16 + k] = p;
                lsum += p;
            }
            lsum += __shfl_xor_sync(0xFFFFFFFFu, lsum, 1);
            lsum += __shfl_xor_sync(0xFFFFFFFFu, lsum, 2);
            if (seg == 0) {
                float cfac = __expf(m_old - mn);
                rowm[row] = mn;
                rowl[row] = rowl[row] * cfac + lsum;
                rowc[row] = cfac;
            }
        }
        __syncthreads();

        // rescale + P@V
        #pragma unroll
        for (int i = 0; i < 8; i++) {
            int r = rb + 8 * i;
            float cfac = rowc[r];
            float4 ov = o[i];
            ov.x *= cfac; ov.y *= cfac; ov.z *= cfac; ov.w *= cfac;
            const float* srow = &Ss[r * SPAD];
            #pragma unroll 4
            for (int k = 0; k < KT; k++) {
                float p = srow[k];
                float4 vv = *(const float4*)&Vs[k * DPAD + cg * 4];
                ov.x += p * vv.x; ov.y += p * vv.y;
                ov.z += p * vv.z; ov.w += p * vv.w;
            }
            o[i] = ov;
        }
        __syncthreads();
    }

    #pragma unroll
    for (int i = 0; i < 8; i++) {
        int r = rb + 8 * i;
        float inv = 1.f / rowl[r];
        float4 ov = o[i];
        size_t idx = ((size_t)(b * Sq + q0 + r)) * Hq + h * HD + cg * 4;
        *(float4*)&ctx[idx] = make_float4(tf32r(ov.x * inv), tf32r(ov.y * inv),
                                          tf32r(ov.z * inv), tf32r(ov.w * inv));
    }
}

// ---------------------------------------------------------------------------
// Launch
// ---------------------------------------------------------------------------
extern "C" void kernel_launch(void* const* d_in, const int* in_sizes, int n_in,
                              void* d_out, int out_size)
{
    const float* hidden  = (const float*)d_in[0];
    const float* w_qkv   = (const float*)d_in[1];
    const float* w_dense = (const float*)d_in[2];
    const float* ln_a_s  = (const float*)d_in[3];
    const float* ln_a_b  = (const float*)d_in[4];
    const float* ln_m_s  = (const float*)d_in[5];
    const float* ln_m_b  = (const float*)d_in[6];
    const float* w_fc    = (const float*)d_in[7];
    const float* w_out   = (const float*)d_in[8];
    const float* sin_tab = (const float*)d_in[9];
    const float* cos_tab = (const float*)d_in[10];
    const int*   amask   = (const int*)d_in[11];
    const int*   pos_ids = (const int*)d_in[12];
    float* out = (float*)d_out;

    float *p_attn_in, *p_mlp_in, *p_qkv, *p_q, *p_k, *p_v, *p_ctx, *p_attn_out, *p_fc;
    float *p_wqkv, *p_wdense, *p_wfc, *p_wout;
    cudaGetSymbolAddress((void**)&p_attn_in,  g_attn_in);
    cudaGetSymbolAddress((void**)&p_mlp_in,   g_mlp_in);
    cudaGetSymbolAddress((void**)&p_qkv,      g_qkv);
    cudaGetSymbolAddress((void**)&p_q,        g_q);
    cudaGetSymbolAddress((void**)&p_k,        g_k);
    cudaGetSymbolAddress((void**)&p_v,        g_v);
    cudaGetSymbolAddress((void**)&p_ctx,      g_ctx);
    cudaGetSymbolAddress((void**)&p_attn_out, g_attn_out);
    cudaGetSymbolAddress((void**)&p_fc,       g_fc);
    cudaGetSymbolAddress((void**)&p_wqkv,     g_wqkv_t);
    cudaGetSymbolAddress((void**)&p_wdense,   g_wdense_t);
    cudaGetSymbolAddress((void**)&p_wfc,      g_wfc_t);
    cudaGetSymbolAddress((void**)&p_wout,     g_wout_t);

    cudaFuncSetAttribute(mma_gemm_kernel<0>, cudaFuncAttributeMaxDynamicSharedMemorySize, GEMM_SMEM);
    cudaFuncSetAttribute(mma_gemm_kernel<1>, cudaFuncAttributeMaxDynamicSharedMemorySize, GEMM_SMEM);
    cudaFuncSetAttribute(mma_gemm_kernel<2>, cudaFuncAttributeMaxDynamicSharedMemorySize, GEMM_SMEM);
    cudaFuncSetAttribute(attn_kernel, cudaFuncAttributeMaxDynamicSharedMemorySize, ATTN_SMEM);

    // 0. transpose + tf32-round weights into [N,K]
    transpose_rna_kernel<<<dim3(QKVW/32, Hq/32), 256>>>(w_qkv,   p_wqkv,   Hq, QKVW);
    transpose_rna_kernel<<<dim3(Hq/32,   Hq/32), 256>>>(w_dense, p_wdense, Hq, Hq);
    transpose_rna_kernel<<<dim3(FF/32,   Hq/32), 256>>>(w_fc,    p_wfc,    Hq, FF);
    transpose_rna_kernel<<<dim3(Hq/32,   FF/32), 256>>>(w_out,   p_wout,   FF, Hq);

    // 1. parallel layernorms (tf32-rounded outputs)
    ln_dual_kernel<<<Mrows, 256>>>(hidden, ln_a_s, ln_a_b, ln_m_s, ln_m_b,
                                   p_attn_in, p_mlp_in);

    // 2. qkv projection
    mma_gemm_kernel<0><<<dim3(Mrows/256, QKVW/128), 256, GEMM_SMEM>>>(
        p_attn_in, p_wqkv, p_qkv, Hq, QKVW, nullptr, nullptr);

    // 3. rope + head split
    rope_kernel<<<Bq * Sq * NKV, 128>>>(p_qkv, sin_tab, cos_tab, pos_ids,
                                        p_q, p_k, p_v);

    // 4. attention
    attn_kernel<<<dim3(Sq / QT, NH, Bq), 256, ATTN_SMEM>>>(
        p_q, p_k, p_v, amask, p_ctx);

    // 5. dense projection
    mma_gemm_kernel<0><<<dim3(Mrows/256, Hq/128), 256, GEMM_SMEM>>>(
        p_ctx, p_wdense, p_attn_out, Hq, Hq, nullptr, nullptr);

    // 6. MLP fc + exact GELU
    mma_gemm_kernel<1><<<dim3(Mrows/256, FF/128), 256, GEMM_SMEM>>>(
        p_mlp_in, p_wfc, p_fc, Hq, FF, nullptr, nullptr);

    // 7. MLP out + parallel residual -> d_out
    mma_gemm_kernel<2><<<dim3(Mrows/256, Hq/128), 256, GEMM_SMEM>>>(
        p_fc, p_wout, out, FF, Hq, hidden, p_attn_out);
}

// round 5
// speedup vs baseline: 4.8519x; 1.6157x over previous
#include <cuda_runtime.h>
#include <cuda_fp16.h>
#include <math.h>
#include <stdint.h>

// ---------------------------------------------------------------------------
// Problem constants
// ---------------------------------------------------------------------------
#define Bq   2
#define Sq   1024
#define Hq   4096
#define NH   32
#define NKV  8
#define HD   128
#define Gq   4
#define QKVW 6144
#define FF   16384
#define Mrows (Bq * Sq)
#define EPS  1e-5f
#define ATTN_SCALE 0.08838834764831845f

// ---------------------------------------------------------------------------
// Helpers
// ---------------------------------------------------------------------------
__device__ __forceinline__ uint32_t smem_u32(const void* p) {
    uint32_t a;
    asm("{ .reg .u64 t; cvta.to.shared.u64 t, %1; cvt.u32.u64 %0, t; }" : "=r"(a) : "l"(p));
    return a;
}
#define CP_ASYNC16(dst, src) \
    asm volatile("cp.async.cg.shared.global [%0], [%1], 16;" :: "r"(dst), "l"(src) : "memory")
#define CP_COMMIT() asm volatile("cp.async.commit_group;" ::: "memory")

__device__ __forceinline__ float tf32r(float x) {
    uint32_t u;
    asm("cvt.rna.tf32.f32 %0, %1;" : "=r"(u) : "f"(x));
    return __uint_as_float(u);
}
__device__ __forceinline__ float gelu_exact(float x) {
    return 0.5f * x * (1.0f + erff(x * 0.7071067811865475f));
}

// fp16 MMA, f32 accumulate: m16n8k16
__device__ __forceinline__ void mma_f16(float* c, uint32_t a0, uint32_t a1,
                                        uint32_t a2, uint32_t a3,
                                        uint32_t b0, uint32_t b1)
{
    asm volatile(
        "mma.sync.aligned.m16n8k16.row.col.f32.f16.f16.f32 "
        "{%0,%1,%2,%3}, {%4,%5,%6,%7}, {%8,%9}, {%0,%1,%2,%3};"
        : "+f"(c[0]), "+f"(c[1]), "+f"(c[2]), "+f"(c[3])
        : "r"(a0), "r"(a1), "r"(a2), "r"(a3), "r"(b0), "r"(b1));
}

// ---------------------------------------------------------------------------
// Scratch (device globals)
// ---------------------------------------------------------------------------
__device__ __half g_attn_in [Mrows * Hq];
__device__ __half g_mlp_in  [Mrows * Hq];
__device__ float  g_qkv     [Mrows * QKVW];
__device__ float  g_q       [(size_t)Bq * NH  * Sq * HD];
__device__ float  g_k       [(size_t)Bq * NKV * Sq * HD];
__device__ float  g_v       [(size_t)Bq * NKV * Sq * HD];
__device__ __half g_ctx     [Mrows * Hq];
__device__ float  g_attn_out[Mrows * Hq];
__device__ __half g_fc      [(size_t)Mrows * FF];
__device__ __half g_wqkv_t  [(size_t)QKVW * Hq];
__device__ __half g_wdense_t[(size_t)Hq * Hq];
__device__ __half g_wfc_t   [(size_t)FF * Hq];
__device__ __half g_wout_t  [(size_t)Hq * FF];

// ---------------------------------------------------------------------------
// Weight transpose + fp16 round: Wt[n,k] = half(W[k,n])
// ---------------------------------------------------------------------------
__global__ void __launch_bounds__(256)
transpose_h_kernel(const float* __restrict__ W, __half* __restrict__ Wt, int Kd, int Nd)
{
    __shared__ float tile[32][33];
    int n0 = blockIdx.x * 32, k0 = blockIdx.y * 32;
    int tx = threadIdx.x & 31, ty = threadIdx.x >> 5;
    #pragma unroll
    for (int r = 0; r < 32; r += 8)
        tile[ty + r][tx] = W[(size_t)(k0 + ty + r) * Nd + n0 + tx];
    __syncthreads();
    #pragma unroll
    for (int r = 0; r < 32; r += 8)
        Wt[(size_t)(n0 + ty + r) * Kd + k0 + tx] = __float2half_rn(tile[tx][ty + r]);
}

// ---------------------------------------------------------------------------
// Dual LayerNorm -> fp16 outputs (GEMM inputs)
// ---------------------------------------------------------------------------
__global__ void __launch_bounds__(256)
ln_dual_kernel(const float* __restrict__ x,
               const float* __restrict__ s1, const float* __restrict__ b1,
               const float* __restrict__ s2, const float* __restrict__ b2,
               __half* __restrict__ o1, __half* __restrict__ o2)
{
    int row = blockIdx.x;
    const float4* xr = (const float4*)(x + (size_t)row * Hq);

    float sum = 0.f, sq = 0.f;
    for (int i = threadIdx.x; i < Hq / 4; i += 256) {
        float4 v = xr[i];
        sum += v.x + v.y + v.z + v.w;
        sq  += v.x*v.x + v.y*v.y + v.z*v.z + v.w*v.w;
    }
    #pragma unroll
    for (int o = 16; o; o >>= 1) {
        sum += __shfl_xor_sync(0xFFFFFFFFu, sum, o);
        sq  += __shfl_xor_sync(0xFFFFFFFFu, sq,  o);
    }
    __shared__ float wsum[8], wsq[8];
    int w = threadIdx.x >> 5, l = threadIdx.x & 31;
    if (l == 0) { wsum[w] = sum; wsq[w] = sq; }
    __syncthreads();
    sum = 0.f; sq = 0.f;
    #pragma unroll
    for (int i = 0; i < 8; i++) { sum += wsum[i]; sq += wsq[i]; }

    float mean = sum * (1.0f / Hq);
    float var  = sq  * (1.0f / Hq) - mean * mean;
    float rstd = rsqrtf(var + EPS);

    const float4* s1r = (const float4*)s1;
    const float4* b1r = (const float4*)b1;
    const float4* s2r = (const float4*)s2;
    const float4* b2r = (const float4*)b2;
    __half2* o1r = (__half2*)(o1 + (size_t)row * Hq);
    __half2* o2r = (__half2*)(o2 + (size_t)row * Hq);

    for (int i = threadIdx.x; i < Hq / 4; i += 256) {
        float4 v = xr[i];
        float4 a = s1r[i], c = b1r[i], d = s2r[i], e = b2r[i];
        float nx = (v.x - mean) * rstd;
        float ny = (v.y - mean) * rstd;
        float nz = (v.z - mean) * rstd;
        float nw = (v.w - mean) * rstd;
        o1r[2*i]   = __floats2half2_rn(nx*a.x + c.x, ny*a.y + c.y);
        o1r[2*i+1] = __floats2half2_rn(nz*a.z + c.z, nw*a.w + c.w);
        o2r[2*i]   = __floats2half2_rn(nx*d.x + e.x, ny*d.y + e.y);
        o2r[2*i+1] = __floats2half2_rn(nz*d.z + e.z, nw*d.w + e.w);
    }
}

// ---------------------------------------------------------------------------
// fp16 mma.sync GEMM: C[M,N] = A[M,K] @ Bt[N,K]^T  (A, Bt fp16; acc f32)
// 256x128x32 CTA tile, 8 warps (4m x 2n), warp tile 64x64 (4x8 m16n8k16).
// 4-stage cp.async ring, one __syncthreads per chunk.
// EPI: 0 none (f32 out), 1 exact GELU (fp16 out), 2 +R1+R2 (f32 out)
// ---------------------------------------------------------------------------
#define SROW 40                       // halves per smem row (32 data + 8 pad)
#define GSTG 4
#define ASZ  (256 * SROW)             // halves
#define BSZ  (128 * SROW)
#define GEMM_SMEM (GSTG * (ASZ + BSZ) * 2)   // 122880 bytes

__device__ __forceinline__ void g_load(const __half* __restrict__ Ag,
                                       const __half* __restrict__ Bg, int K,
                                       __half* As, __half* Bs, int k0, int tid)
{
    int c8 = (tid & 3) * 8;             // half offset within 32-half row
    int rA = tid >> 2;                  // 0..63
    #pragma unroll
    for (int j = 0; j < 4; j++) {
        int r = rA + j * 64;
        CP_ASYNC16(smem_u32(&As[r * SROW + c8]), Ag + (size_t)r * K + k0 + c8);
    }
    #pragma unroll
    for (int j = 0; j < 2; j++) {
        int r = rA + j * 64;
        CP_ASYNC16(smem_u32(&Bs[r * SROW + c8]), Bg + (size_t)r * K + k0 + c8);
    }
    CP_COMMIT();
}

template <int EPI>
__global__ void __launch_bounds__(256, 1)
mma_gemm_kernel(const __half* __restrict__ A, const __half* __restrict__ Bt,
                void* __restrict__ Cv, int K, int N,
                const float* __restrict__ R1, const float* __restrict__ R2)
{
    extern __shared__ __half gsm[];
    __half* AsB = gsm;                    // [GSTG][ASZ]
    __half* BsB = gsm + GSTG * ASZ;       // [GSTG][BSZ]

    int tid = threadIdx.x;
    int lane = tid & 31;
    int wid = tid >> 5;
    int wm = (wid & 3) * 64;
    int wn = (wid >> 2) * 64;
    int lr = lane >> 2;
    int lc = lane & 3;
    int m0 = blockIdx.x * 256;
    int n0 = blockIdx.y * 128;

    const __half* Ag = A  + (size_t)m0 * K;
    const __half* Bg = Bt + (size_t)n0 * K;

    float acc[4][8][4];
    #pragma unroll
    for (int i = 0; i < 4; i++)
        #pragma unroll
        for (int j = 0; j < 8; j++)
            #pragma unroll
            for (int q = 0; q < 4; q++) acc[i][j][q] = 0.f;

    const int NC = K / 32;
    g_load(Ag, Bg, K, AsB + 0 * ASZ, BsB + 0 * BSZ,  0, tid);
    g_load(Ag, Bg, K, AsB + 1 * ASZ, BsB + 1 * BSZ, 32, tid);
    g_load(Ag, Bg, K, AsB + 2 * ASZ, BsB + 2 * BSZ, 64, tid);

    for (int c = 0; c < NC; c++) {
        if (c + 2 < NC) asm volatile("cp.async.wait_group 2;" ::: "memory");
        else            asm volatile("cp.async.wait_group 0;" ::: "memory");
        __syncthreads();

        if (c + 3 < NC)
            g_load(Ag, Bg, K, AsB + ((c + 3) & 3) * ASZ, BsB + ((c + 3) & 3) * BSZ,
                   (c + 3) * 32, tid);

        const __half* Ast = AsB + (c & 3) * ASZ;
        const __half* Bst = BsB + (c & 3) * BSZ;

        #pragma unroll
        for (int ks = 0; ks < 2; ks++) {
            int ko = ks * 16;
            uint32_t af[4][4];
            #pragma unroll
            for (int i = 0; i < 4; i++) {
                const __half* ab = &Ast[(wm + i * 16 + lr) * SROW + ko + lc * 2];
                af[i][0] = *(const uint32_t*)(ab);
                af[i][1] = *(const uint32_t*)(ab + 8 * SROW);
                af[i][2] = *(const uint32_t*)(ab + 8);
                af[i][3] = *(const uint32_t*)(ab + 8 * SROW + 8);
            }
            #pragma unroll
            for (int j = 0; j < 8; j++) {
                const __half* bb = &Bst[(wn + j * 8 + lr) * SROW + ko + lc * 2];
                uint32_t b0 = *(const uint32_t*)(bb);
                uint32_t b1 = *(const uint32_t*)(bb + 8);
                #pragma unroll
                for (int i = 0; i < 4; i++)
                    mma_f16(acc[i][j], af[i][0], af[i][1], af[i][2], af[i][3], b0, b1);
            }
        }
    }

    // epilogue
    #pragma unroll
    for (int i = 0; i < 4; i++) {
        #pragma unroll
        for (int j = 0; j < 8; j++) {
            int r0 = m0 + wm + i * 16 + lr;
            int cc = n0 + wn + j * 8 + lc * 2;
            float x0 = acc[i][j][0], x1 = acc[i][j][1];
            float x2 = acc[i][j][2], x3 = acc[i][j][3];
            if (EPI == 1) {
                // GELU -> fp16 out
                __half* Ch = (__half*)Cv;
                *(__half2*)(Ch + (size_t)r0 * N + cc) =
                    __floats2half2_rn(gelu_exact(x0), gelu_exact(x1));
                *(__half2*)(Ch + (size_t)(r0 + 8) * N + cc) =
                    __floats2half2_rn(gelu_exact(x2), gelu_exact(x3));
            } else {
                float* Cf = (float*)Cv;
                if (EPI == 2) {
                    size_t i0 = (size_t)r0 * N + cc;
                    size_t i1 = (size_t)(r0 + 8) * N + cc;
                    float2 a0 = *(const float2*)(R1 + i0);
                    float2 a1 = *(const float2*)(R1 + i1);
                    float2 d0 = *(const float2*)(R2 + i0);
                    float2 d1 = *(const float2*)(R2 + i1);
                    x0 += a0.x + d0.x; x1 += a0.y + d0.y;
                    x2 += a1.x + d1.x; x3 += a1.y + d1.y;
                }
                *(float2*)(Cf + (size_t)r0 * N + cc)       = make_float2(x0, x1);
                *(float2*)(Cf + (size_t)(r0 + 8) * N + cc) = make_float2(x2, x3);
            }
        }
    }
}

// ---------------------------------------------------------------------------
// RoPE + head split (reads f32 qkv GEMM output)
// ---------------------------------------------------------------------------
__global__ void __launch_bounds__(128)
rope_kernel(const float* __restrict__ qkv,
            const float* __restrict__ sint, const float* __restrict__ cost,
            const int* __restrict__ pos_ids,
            float* __restrict__ Qo, float* __restrict__ Ko, float* __restrict__ Vo)
{
    int d = threadIdx.x;
    int idx = blockIdx.x;
    int kvh = idx % NKV; idx /= NKV;
    int s = idx % Sq;
    int b = idx / Sq;

    int pos = pos_ids[b * Sq + s];
    float sn = sint[pos * HD + d];
    float cs = cost[pos * HD + d];
    int dro = (d < 64) ? (d + 64) : (d - 64);
    float sgn = (d < 64) ? -1.f : 1.f;

    const float* base = qkv + (size_t)(b * Sq + s) * QKVW + kvh * (Gq + 2) * HD;

    float kx = base[Gq * HD + d];
    float ko = base[Gq * HD + dro];
    size_t kvidx = ((size_t)(b * NKV + kvh) * Sq + s) * HD + d;
    Ko[kvidx] = kx * cs + sgn * ko * sn;
    Vo[kvidx] = base[(Gq + 1) * HD + d];

    #pragma unroll
    for (int g = 0; g < Gq; g++) {
        int h = kvh * Gq + g;
        float qx = base[g * HD + d];
        float qo = base[g * HD + dro];
        Qo[((size_t)(b * NH + h) * Sq + s) * HD + d] = qx * cs + sgn * qo * sn;
    }
}

// ---------------------------------------------------------------------------
// Flash attention (fp32; ctx written as fp16 for dense GEMM input)
// ---------------------------------------------------------------------------
#define QT 64
#define KT 64
#define DPAD 132
#define SPAD 66
#define ATTN_SMEM ((3 * QT * DPAD + QT * SPAD + 3 * QT) * 4)

__global__ void __launch_bounds__(256)
attn_kernel(const float* __restrict__ Q, const float* __restrict__ Kg,
            const float* __restrict__ Vg, const int* __restrict__ amask,
            __half* __restrict__ ctx)
{
    extern __shared__ float sm[];
    float* Qs   = sm;
    float* Ks   = Qs + QT * DPAD;
    float* Vs   = Ks + KT * DPAD;
    float* Ss   = Vs + KT * DPAD;
    float* rowm = Ss + QT * SPAD;
    float* rowl = rowm + QT;
    float* rowc = rowl + QT;

    int t  = threadIdx.x;
    int q0 = blockIdx.x * QT;
    int h  = blockIdx.y;
    int b  = blockIdx.z;
    int kv = h >> 2;

    const float* Qb = Q  + ((size_t)(b * NH  + h ) * Sq + q0) * HD;
    const float* Kb = Kg + ((size_t)(b * NKV + kv) * Sq) * HD;
    const float* Vb = Vg + ((size_t)(b * NKV + kv) * Sq) * HD;

    for (int i = t; i < QT * (HD / 4); i += 256) {
        int r = i >> 5;
        int c = (i & 31) * 4;
        *(float4*)&Qs[r * DPAD + c] = *(const float4*)(Qb + (size_t)r * HD + c);
    }
    if (t < QT) { rowm[t] = -1e30f; rowl[t] = 0.f; }

    float4 o[8];
    #pragma unroll
    for (int i = 0; i < 8; i++) o[i] = make_float4(0.f, 0.f, 0.f, 0.f);

    int cg = t & 31;
    int rb = t >> 5;
    int qr = t >> 2;
    int kb = t & 3;

    __syncthreads();

    int kend = q0 + QT;
    for (int k0 = 0; k0 < kend; k0 += KT) {
        for (int i = t; i < KT * (HD / 4); i += 256) {
            int r = i >> 5;
            int c = (i & 31) * 4;
            *(float4*)&Ks[r * DPAD + c] = *(const float4*)(Kb + (size_t)(k0 + r) * HD + c);
            *(float4*)&Vs[r * DPAD + c] = *(const float4*)(Vb + (size_t)(k0 + r) * HD + c);
        }
        __syncthreads();

        float acc[16];
        #pragma unroll
        for (int j = 0; j < 16; j++) acc[j] = 0.f;
        const float4* qrow = (const float4*)&Qs[qr * DPAD];
        for (int d4 = 0; d4 < 32; d4++) {
            float4 qv = qrow[d4];
            #pragma unroll
            for (int j = 0; j < 16; j++) {
                float4 kvv = *(const float4*)&Ks[(kb + 4 * j) * DPAD + d4 * 4];
                acc[j] += qv.x * kvv.x + qv.y * kvv.y + qv.z * kvv.z + qv.w * kvv.w;
            }
        }
        int qg = q0 + qr;
        #pragma unroll
        for (int j = 0; j < 16; j++) {
            int kk = kb + 4 * j;
            int kg = k0 + kk;
            bool valid = (kg <= qg) && (amask[b * Sq + kg] > 0);
            Ss[qr * SPAD + kk] = valid ? acc[j] * ATTN_SCALE : -1e30f;
        }
        __syncthreads();

        // online softmax: 4 threads per row
        {
            int row = t >> 2, seg = t & 3;
            float* srow = &Ss[row * SPAD];
            float m_old = rowm[row];
            float m = -1e30f;
            #pragma unroll
            for (int k = 0; k < 16; k++) m = fmaxf(m, srow[seg * 16 + k]);
            m = fmaxf(m, __shfl_xor_sync(0xFFFFFFFFu, m, 1));
            m = fmaxf(m, __shfl_xor_sync(0xFFFFFFFFu, m, 2));
            float mn = fmaxf(m_old, m);
            float lsum = 0.f;
            #pragma unroll
            for (int k = 0; k < 16; k++) {
                float p = __expf(srow[seg * 16 + k] - mn);
                srow[seg * 16 + k] = p;
                lsum += p;
            }
            lsum += __shfl_xor_sync(0xFFFFFFFFu, lsum, 1);
            lsum += __shfl_xor_sync(0xFFFFFFFFu, lsum, 2);
            if (seg == 0) {
                float cfac = __expf(m_old - mn);
                rowm[row] = mn;
                rowl[row] = rowl[row] * cfac + lsum;
                rowc[row] = cfac;
            }
        }
        __syncthreads();

        #pragma unroll
        for (int i = 0; i < 8; i++) {
            int r = rb + 8 * i;
            float cfac = rowc[r];
            float4 ov = o[i];
            ov.x *= cfac; ov.y *= cfac; ov.z *= cfac; ov.w *= cfac;
            const float* srow = &Ss[r * SPAD];
            #pragma unroll 4
            for (int k = 0; k < KT; k++) {
                float p = srow[k];
                float4 vv = *(const float4*)&Vs[k * DPAD + cg * 4];
                ov.x += p * vv.x; ov.y += p * vv.y;
                ov.z += p * vv.z; ov.w += p * vv.w;
            }
            o[i] = ov;
        }
        __syncthreads();
    }

    #pragma unroll
    for (int i = 0; i < 8; i++) {
        int r = rb + 8 * i;
        float inv = 1.f / rowl[r];
        float4 ov = o[i];
        size_t idx = ((size_t)(b * Sq + q0 + r)) * Hq + h * HD + cg * 4;
        *(__half2*)&ctx[idx]     = __floats2half2_rn(ov.x * inv, ov.y * inv);
        *(__half2*)&ctx[idx + 2] = __floats2half2_rn(ov.z * inv, ov.w * inv);
    }
}

// ---------------------------------------------------------------------------
// Launch
// ---------------------------------------------------------------------------
extern "C" void kernel_launch(void* const* d_in, const int* in_sizes, int n_in,
                              void* d_out, int out_size)
{
    const float* hidden  = (const float*)d_in[0];
    const float* w_qkv   = (const float*)d_in[1];
    const float* w_dense = (const float*)d_in[2];
    const float* ln_a_s  = (const float*)d_in[3];
    const float* ln_a_b  = (const float*)d_in[4];
    const float* ln_m_s  = (const float*)d_in[5];
    const float* ln_m_b  = (const float*)d_in[6];
    const float* w_fc    = (const float*)d_in[7];
    const float* w_out   = (const float*)d_in[8];
    const float* sin_tab = (const float*)d_in[9];
    const float* cos_tab = (const float*)d_in[10];
    const int*   amask   = (const int*)d_in[11];
    const int*   pos_ids = (const int*)d_in[12];
    float* out = (float*)d_out;

    __half *p_attn_in, *p_mlp_in, *p_ctx, *p_fc;
    __half *p_wqkv, *p_wdense, *p_wfc, *p_wout;
    float *p_qkv, *p_q, *p_k, *p_v, *p_attn_out;
    cudaGetSymbolAddress((void**)&p_attn_in,  g_attn_in);
    cudaGetSymbolAddress((void**)&p_mlp_in,   g_mlp_in);
    cudaGetSymbolAddress((void**)&p_qkv,      g_qkv);
    cudaGetSymbolAddress((void**)&p_q,        g_q);
    cudaGetSymbolAddress((void**)&p_k,        g_k);
    cudaGetSymbolAddress((void**)&p_v,        g_v);
    cudaGetSymbolAddress((void**)&p_ctx,      g_ctx);
    cudaGetSymbolAddress((void**)&p_attn_out, g_attn_out);
    cudaGetSymbolAddress((void**)&p_fc,       g_fc);
    cudaGetSymbolAddress((void**)&p_wqkv,     g_wqkv_t);
    cudaGetSymbolAddress((void**)&p_wdense,   g_wdense_t);
    cudaGetSymbolAddress((void**)&p_wfc,      g_wfc_t);
    cudaGetSymbolAddress((void**)&p_wout,     g_wout_t);

    cudaFuncSetAttribute(mma_gemm_kernel<0>, cudaFuncAttributeMaxDynamicSharedMemorySize, GEMM_SMEM);
    cudaFuncSetAttribute(mma_gemm_kernel<1>, cudaFuncAttributeMaxDynamicSharedMemorySize, GEMM_SMEM);
    cudaFuncSetAttribute(mma_gemm_kernel<2>, cudaFuncAttributeMaxDynamicSharedMemorySize, GEMM_SMEM);
    cudaFuncSetAttribute(attn_kernel, cudaFuncAttributeMaxDynamicSharedMemorySize, ATTN_SMEM);

    // 0. transpose + fp16-round weights into [N,K]
    transpose_h_kernel<<<dim3(QKVW/32, Hq/32), 256>>>(w_qkv,   p_wqkv,   Hq, QKVW);
    transpose_h_kernel<<<dim3(Hq/32,   Hq/32), 256>>>(w_dense, p_wdense, Hq, Hq);
    transpose_h_kernel<<<dim3(FF/32,   Hq/32), 256>>>(w_fc,    p_wfc,    Hq, FF);
    transpose_h_kernel<<<dim3(Hq/32,   FF/32), 256>>>(w_out,   p_wout,   FF, Hq);

    // 1. parallel layernorms (fp16 outputs)
    ln_dual_kernel<<<Mrows, 256>>>(hidden, ln_a_s, ln_a_b, ln_m_s, ln_m_b,
                                   p_attn_in, p_mlp_in);

    // 2. qkv projection (fp16 mma, f32 out)
    mma_gemm_kernel<0><<<dim3(Mrows/256, QKVW/128), 256, GEMM_SMEM>>>(
        p_attn_in, p_wqkv, p_qkv, Hq, QKVW, nullptr, nullptr);

    // 3. rope + head split
    rope_kernel<<<Bq * Sq * NKV, 128>>>(p_qkv, sin_tab, cos_tab, pos_ids,
                                        p_q, p_k, p_v);

    // 4. attention (ctx -> fp16)
    attn_kernel<<<dim3(Sq / QT, NH, Bq), 256, ATTN_SMEM>>>(
        p_q, p_k, p_v, amask, p_ctx);

    // 5. dense projection (f32 out)
    mma_gemm_kernel<0><<<dim3(Mrows/256, Hq/128), 256, GEMM_SMEM>>>(
        p_ctx, p_wdense, p_attn_out, Hq, Hq, nullptr, nullptr);

    // 6. MLP fc + exact GELU (fp16 out)
    mma_gemm_kernel<1><<<dim3(Mrows/256, FF/128), 256, GEMM_SMEM>>>(
        p_mlp_in, p_wfc, p_fc, Hq, FF, nullptr, nullptr);

    // 7. MLP out + parallel residual -> d_out (f32)
    mma_gemm_kernel<2><<<dim3(Mrows/256, Hq/128), 256, GEMM_SMEM>>>(
        p_fc, p_wout, out, FF, Hq, hidden, p_attn_out);
}